// round 17
// baseline (speedup 1.0000x reference)
#include <cuda_runtime.h>
#include <cuda_fp16.h>
#include <stdint.h>

#define B_   16
#define LK_  2048
#define LQ_  256
#define DIM_ 512
#define H_   8
#define DK_  64
#define M_   (B_ * LQ_)     // 4096

// q scale folded with log2(e): S lands in log2 domain
#define QSCALE (0.00552427172801990775f * 1.44269504088896341f)

// ---------------- helpers ----------------
__device__ __forceinline__ uint32_t pack_h2(float x, float y) {
    __half2 h = __float22half2_rn(make_float2(x, y));
    return *(uint32_t*)&h;
}
__device__ __forceinline__ void pack_split_h(float x, float y,
                                             uint32_t& hi, uint32_t& lo) {
    __half2 h = __float22half2_rn(make_float2(x, y));
    float2 hf = __half22float2(h);
    __half2 l = __float22half2_rn(make_float2(x - hf.x, y - hf.y));
    hi = *(uint32_t*)&h;
    lo = *(uint32_t*)&l;
}
__device__ __forceinline__ uint32_t ex2h2(uint32_t x) {
    uint32_t r; asm("ex2.approx.f16x2 %0, %1;" : "=r"(r) : "r"(x)); return r;
}
__device__ __forceinline__ void ldsm4(uint32_t* r, uint32_t addr) {
    asm volatile("ldmatrix.sync.aligned.m8n8.x4.shared.b16 {%0,%1,%2,%3}, [%4];"
        : "=r"(r[0]), "=r"(r[1]), "=r"(r[2]), "=r"(r[3]) : "r"(addr));
}
__device__ __forceinline__ void ldsm4t(uint32_t* r, uint32_t addr) {
    asm volatile("ldmatrix.sync.aligned.m8n8.x4.trans.shared.b16 {%0,%1,%2,%3}, [%4];"
        : "=r"(r[0]), "=r"(r[1]), "=r"(r[2]), "=r"(r[3]) : "r"(addr));
}
__device__ __forceinline__ void mma16816(float* c, const uint32_t* a,
                                         uint32_t b0, uint32_t b1) {
    asm volatile("mma.sync.aligned.m16n8k16.row.col.f32.f16.f16.f32 "
        "{%0,%1,%2,%3}, {%4,%5,%6,%7}, {%8,%9}, {%0,%1,%2,%3};"
        : "+f"(c[0]), "+f"(c[1]), "+f"(c[2]), "+f"(c[3])
        : "r"(a[0]), "r"(a[1]), "r"(a[2]), "r"(a[3]), "r"(b0), "r"(b1));
}
__device__ __forceinline__ void mma16816h(uint32_t* c, const uint32_t* a,
                                          uint32_t b0, uint32_t b1) {
    asm volatile("mma.sync.aligned.m16n8k16.row.col.f16.f16.f16.f16 "
        "{%0,%1}, {%2,%3,%4,%5}, {%6,%7}, {%0,%1};"
        : "+r"(c[0]), "+r"(c[1])
        : "r"(a[0]), "r"(a[1]), "r"(a[2]), "r"(a[3]), "r"(b0), "r"(b1));
}
__device__ __forceinline__ void cp16(uint32_t dst, const void* src) {
    asm volatile("cp.async.cg.shared.global [%0], [%1], 16;" :: "r"(dst), "l"(src));
}

// ---------------- scratch (__device__ globals) ----------------
__device__ __half g_xh [M_ * DIM_];
__device__ __half g_wqh[DIM_ * DIM_];
__device__ __half g_woh[DIM_ * DIM_], g_wol[DIM_ * DIM_];

// ---------------------------------------------------------------------------
// Prep (weights only): Wq -> fp16; Wo -> fp16 hi/lo.  MLP=4 per thread.
// ---------------------------------------------------------------------------
#define NW16 (DIM_ * DIM_ / 16)    // 16384

__global__ void prep_kernel(const float* __restrict__ Wq,
                            const float* __restrict__ Wo) {
    int i = blockIdx.x * blockDim.x + threadIdx.x;
    if (i < NW16) {
        const float4* src = (const float4*)Wq + (size_t)i * 4;
        float4 v0 = src[0], v1 = src[1], v2 = src[2], v3 = src[3];
        uint4* dst = (uint4*)g_wqh + (size_t)i * 2;
        dst[0] = make_uint4(pack_h2(v0.x, v0.y), pack_h2(v0.z, v0.w),
                            pack_h2(v1.x, v1.y), pack_h2(v1.z, v1.w));
        dst[1] = make_uint4(pack_h2(v2.x, v2.y), pack_h2(v2.z, v2.w),
                            pack_h2(v3.x, v3.y), pack_h2(v3.z, v3.w));
    } else if (i < 2 * NW16) {
        int j = i - NW16;
        const float4* src = (const float4*)Wo + (size_t)j * 4;
        float4 v[4] = {src[0], src[1], src[2], src[3]};
        uint32_t hi[8], lo[8];
        #pragma unroll
        for (int k = 0; k < 4; ++k) {
            pack_split_h(v[k].x, v[k].y, hi[2 * k],     lo[2 * k]);
            pack_split_h(v[k].z, v[k].w, hi[2 * k + 1], lo[2 * k + 1]);
        }
        uint4* dh = (uint4*)g_woh + (size_t)j * 2;
        uint4* dl = (uint4*)g_wol + (size_t)j * 2;
        dh[0] = make_uint4(hi[0], hi[1], hi[2], hi[3]);
        dh[1] = make_uint4(hi[4], hi[5], hi[6], hi[7]);
        dl[0] = make_uint4(lo[0], lo[1], lo[2], lo[3]);
        dl[1] = make_uint4(lo[4], lo[5], lo[6], lo[7]);
    }
}

// ---------------------------------------------------------------------------
// GEMM 2-term (output projection) — R11 structure; Wl term on fp16
// accumulators (correction magnitudes ~1e-3, fp16-acc error negligible).
// ---------------------------------------------------------------------------
#define G2_STAGE 16384
#define G2_WH    8192
#define G2_WL    12288
#define GEMM2_SMEM (3 * G2_STAGE)   // 48 KB

__global__ __launch_bounds__(256, 2)
void gemm2_kernel(const __half* __restrict__ Ah,
                  const __half* __restrict__ Wh,
                  const __half* __restrict__ Wl,
                  const float* __restrict__ bias,
                  float* __restrict__ C) {
    extern __shared__ char sm[];
    const uint32_t sb = (uint32_t)__cvta_generic_to_shared(sm);
    const int tid = threadIdx.x, wid = tid >> 5, lane = tid & 31;
    const int g = lane >> 2, t = lane & 3;
    const int wm = wid & 3, wn = wid >> 2;
    const int n0 = blockIdx.x * 64, m0 = blockIdx.y * 128;

    auto issue = [&](int kb, int st) {
        uint32_t base = sb + (uint32_t)st * G2_STAGE;
        #pragma unroll
        for (int i = 0; i < 2; ++i) {
            int lin = tid + i * 256;
            int row = lin >> 2, c = lin & 3;
            uint32_t off = (uint32_t)(row * 64 + c * 16);
            off ^= (off >> 3) & 0x30;
            cp16(base + off, Ah + (size_t)(m0 + row) * DIM_ + kb * 32 + c * 8);
        }
        {
            int row = tid >> 3, c = tid & 7;
            uint32_t off = (uint32_t)(row * 128 + c * 16);
            off ^= (off >> 3) & 0x70;
            size_t src = (size_t)(kb * 32 + row) * DIM_ + n0 + c * 8;
            cp16(base + G2_WH + off, Wh + src);
            cp16(base + G2_WL + off, Wl + src);
        }
        asm volatile("cp.async.commit_group;");
    };

    float acc[2][4][4];
    uint32_t accl[2][4][2];   // fp16 accumulators for the Wl correction term
    #pragma unroll
    for (int i = 0; i < 2; ++i)
        #pragma unroll
        for (int j = 0; j < 4; ++j) {
            #pragma unroll
            for (int r = 0; r < 4; ++r) acc[i][j][r] = 0.f;
            accl[i][j][0] = 0u; accl[i][j][1] = 0u;
        }

    const uint32_t aColByte = (uint32_t)((lane >> 4) * 16);
    const uint32_t xr    = (uint32_t)(lane & 7) << 4;
    const uint32_t wRowB = (uint32_t)((lane & 15) * 128);
    const uint32_t wD    = (uint32_t)((lane >> 4) * 16);
    const uint32_t wCol  = (uint32_t)(wn * 64);

    issue(0, 0);
    issue(1, 1);

    for (int kb = 0; kb < 16; ++kb) {
        asm volatile("cp.async.wait_group 1;");
        __syncthreads();
        if (kb + 2 < 16) issue(kb + 2, (kb + 2) % 3);

        uint32_t base = sb + (uint32_t)(kb % 3) * G2_STAGE;
        #pragma unroll
        for (int s = 0; s < 2; ++s) {
            uint32_t af[2][4];
            #pragma unroll
            for (int mf = 0; mf < 2; ++mf) {
                uint32_t off = (uint32_t)((wm * 32 + mf * 16 + (lane & 15)) * 64)
                             + (uint32_t)(s * 32) + aColByte;
                off ^= (off >> 3) & 0x30;
                ldsm4(af[mf], base + off);
            }
            #pragma unroll
            for (int nq = 0; nq < 2; ++nq) {
                uint32_t wo = (uint32_t)(s * 16 * 128) + wRowB +
                              ((wCol + (uint32_t)(nq * 32) + wD) ^ xr);
                uint32_t bh[4], bl[4];
                ldsm4t(bh, base + G2_WH + wo);
                ldsm4t(bl, base + G2_WL + wo);
                #pragma unroll
                for (int mf = 0; mf < 2; ++mf) {
                    mma16816(acc[mf][2 * nq],     af[mf], bh[0], bh[1]);
                    mma16816(acc[mf][2 * nq + 1], af[mf], bh[2], bh[3]);
                    mma16816h(accl[mf][2 * nq],     af[mf], bl[0], bl[1]);
                    mma16816h(accl[mf][2 * nq + 1], af[mf], bl[2], bl[3]);
                }
            }
        }
        __syncthreads();
    }

    #pragma unroll
    for (int mf = 0; mf < 2; ++mf) {
        int r0 = m0 + wm * 32 + mf * 16 + g;
        #pragma unroll
        for (int nj = 0; nj < 4; ++nj) {
            int c = n0 + wn * 32 + nj * 8 + 2 * t;
            float2 bv = *(const float2*)&bias[c];
            float2 l0 = __half22float2(*(__half2*)&accl[mf][nj][0]);
            float2 l1 = __half22float2(*(__half2*)&accl[mf][nj][1]);
            *(float2*)&C[(size_t)r0 * DIM_ + c] =
                make_float2(acc[mf][nj][0] + l0.x + bv.x,
                            acc[mf][nj][1] + l0.y + bv.y);
            *(float2*)&C[(size_t)(r0 + 8) * DIM_ + c] =
                make_float2(acc[mf][nj][2] + l1.x + bv.x,
                            acc[mf][nj][3] + l1.y + bv.y);
        }
    }
}

// ---------------------------------------------------------------------------
// Fused Q-projection + FA2 attention.
// Prologue now consumes fp32 G directly (register prefetch + cvt + STS,
// the mainloop's proven pattern); Wq stays 3-stage cp.async.
// smem: A double buffer 2x8KB @0, Wq ring 3x4KB @16384 -> 28KB.
// Mainloop identical to R14/R15 (fp16-acc S, ex2.f16x2, l ones-mma).
// ---------------------------------------------------------------------------
#define ONES_H2  0x3C003C00u

__global__ __launch_bounds__(256, 2)
void attn_fused_kernel(const float* __restrict__ Lp,
                       const float* __restrict__ Gp,
                       const __half* __restrict__ Wqh,
                       const float* __restrict__ bq,
                       __half* __restrict__ Xh) {
    __shared__ __align__(128) char smem_raw[28672];

    const int tid  = threadIdx.x;
    const int wid  = tid >> 5;
    const int lane = tid & 31;
    const int g = lane >> 2, t = lane & 3;
    const int qb = blockIdx.x, h = blockIdx.y, b = blockIdx.z;

    const uint32_t sb = (uint32_t)__cvta_generic_to_shared(smem_raw);

    const uint32_t xr    = (uint32_t)(lane & 7) << 4;
    const uint32_t wD    = (uint32_t)((lane >> 4) * 16);
    const uint32_t wRowB = (uint32_t)((lane & 15) * 128);
    const uint32_t aColByte = (uint32_t)((lane >> 4) * 16);

    // ======================= Q-projection prologue =======================
    uint32_t qa[4][4];
    {
        const int m0 = (b * 2 + qb) * 128;
        const int n0 = h * DK_;

        float4 pfA[4];
        auto ldA = [&](int kb) {
            const float* s0 = Gp + (size_t)(m0 + (tid >> 2)) * DIM_
                                 + kb * 32 + (tid & 3) * 8;
            pfA[0] = *(const float4*)s0;
            pfA[1] = *(const float4*)(s0 + 4);
            const float* s1 = s0 + (size_t)64 * DIM_;
            pfA[2] = *(const float4*)s1;
            pfA[3] = *(const float4*)(s1 + 4);
        };
        auto stA = [&](int buf) {
            uint32_t o0 = (uint32_t)((tid >> 2) * 64 + (tid & 3) * 16);
            o0 ^= (o0 >> 3) & 0x30;
            *(uint4*)(smem_raw + buf * 8192 + o0) =
                make_uint4(pack_h2(pfA[0].x, pfA[0].y), pack_h2(pfA[0].z, pfA[0].w),
                           pack_h2(pfA[1].x, pfA[1].y), pack_h2(pfA[1].z, pfA[1].w));
            uint32_t o1 = (uint32_t)(((tid >> 2) + 64) * 64 + (tid & 3) * 16);
            o1 ^= (o1 >> 3) & 0x30;
            *(uint4*)(smem_raw + buf * 8192 + o1) =
                make_uint4(pack_h2(pfA[2].x, pfA[2].y), pack_h2(pfA[2].z, pfA[2].w),
                           pack_h2(pfA[3].x, pfA[3].y), pack_h2(pfA[3].z, pfA[3].w));
        };
        auto issueW = [&](int kb, int st) {
            int row = tid >> 3, c = tid & 7;
            uint32_t off = (uint32_t)(row * 128 + c * 16);
            off ^= (off >> 3) & 0x70;
            cp16(sb + 16384u + (uint32_t)st * 4096 + off,
                 Wqh + (size_t)(kb * 32 + row) * DIM_ + n0 + c * 8);
            asm volatile("cp.async.commit_group;");
        };

        float acc[8][4];
        #pragma unroll
        for (int j = 0; j < 8; ++j) {
            acc[j][0] = 0.f; acc[j][1] = 0.f; acc[j][2] = 0.f; acc[j][3] = 0.f;
        }

        issueW(0, 0);
        issueW(1, 1);
        ldA(0); stA(0);
        ldA(1);

        for (int kb = 0; kb < 16; ++kb) {
            asm volatile("cp.async.wait_group 1;");
            __syncthreads();
            if (kb + 2 < 16) issueW(kb + 2, (kb + 2) % 3);

            uint32_t abase = sb + (uint32_t)((kb & 1) * 8192);
            uint32_t wbase = sb + 16384u + (uint32_t)((kb % 3) * 4096);
            #pragma unroll
            for (int s = 0; s < 2; ++s) {
                uint32_t af[4];
                {
                    uint32_t off = (uint32_t)((wid * 16 + (lane & 15)) * 64)
                                 + (uint32_t)(s * 32) + aColByte;
                    off ^= (off >> 3) & 0x30;
                    ldsm4(af, abase + off);
                }
                #pragma unroll
                for (int nq = 0; nq < 4; ++nq) {
                    uint32_t wo = (uint32_t)(s * 2048) + wRowB +
                                  (((uint32_t)(nq * 32) + wD) ^ xr);
                    uint32_t bh[4];
                    ldsm4t(bh, wbase + wo);
                    mma16816(acc[2 * nq],     af, bh[0], bh[1]);
                    mma16816(acc[2 * nq + 1], af, bh[2], bh[3]);
                }
            }
            if (kb < 15) {
                stA((kb + 1) & 1);
                if (kb + 2 < 16) ldA(kb + 2);
            }
        }

        #pragma unroll
        for (int s = 0; s < 4; ++s) {
            float2 b0 = *(const float2*)&bq[h * DK_ + (2 * s) * 8 + 2 * t];
            float2 b1 = *(const float2*)&bq[h * DK_ + (2 * s + 1) * 8 + 2 * t];
            qa[s][0] = pack_h2((acc[2 * s][0] + b0.x) * QSCALE,
                               (acc[2 * s][1] + b0.y) * QSCALE);
            qa[s][1] = pack_h2((acc[2 * s][2] + b0.x) * QSCALE,
                               (acc[2 * s][3] + b0.y) * QSCALE);
            qa[s][2] = pack_h2((acc[2 * s + 1][0] + b1.x) * QSCALE,
                               (acc[2 * s + 1][1] + b1.y) * QSCALE);
            qa[s][3] = pack_h2((acc[2 * s + 1][2] + b1.x) * QSCALE,
                               (acc[2 * s + 1][3] + b1.y) * QSCALE);
        }
    }
    __syncthreads();

    // ======================= attention mainloop =====================
    const int lr0 = tid >> 4;
    const int ld4 = (tid & 15) * 4;
    const float* lbase = Lp + (size_t)b * LK_ * DIM_ + h * DK_;

    float4 pf[4];
    #pragma unroll
    for (int it = 0; it < 4; ++it)
        pf[it] = *(const float4*)&lbase[(size_t)(lr0 + it * 16) * DIM_ + ld4];

    auto store_half = [&](int buf) {
        #pragma unroll
        for (int it = 0; it < 4; ++it) {
            int r = lr0 + it * 16;
            uint32_t off = (uint32_t)(r * 128 + ld4 * 2);
            off = off ^ ((off >> 3) & 0x70);
            *(uint2*)(smem_raw + buf * 8192 + off) =
                make_uint2(pack_h2(pf[it].x, pf[it].y), pack_h2(pf[it].z, pf[it].w));
        }
    };
    auto load_half = [&](int j) {
        #pragma unroll
        for (int it = 0; it < 4; ++it)
            pf[it] = *(const float4*)
                &lbase[(size_t)(j * 64 + lr0 + it * 16) * DIM_ + ld4];
    };

    float oacc[8][4];
    #pragma unroll
    for (int i = 0; i < 8; ++i)
        #pragma unroll
        for (int j = 0; j < 4; ++j) oacc[i][j] = 0.f;
    float lfrag[4] = {0.f, 0.f, 0.f, 0.f};

    const uint32_t sRow  = (uint32_t)(lane & 7) * 128;
    const uint32_t sOff0 = sRow + ((((uint32_t)(lane >> 3)) * 16 +  0) ^ xr);
    const uint32_t sOff1 = sRow + ((((uint32_t)(lane >> 3)) * 16 + 64) ^ xr);
    const uint32_t vRow  = (uint32_t)(lane & 15) * 128;

    store_half(0);
    load_half(1);
    __syncthreads();

    for (int i = 0; i < 32; ++i) {
        const uint32_t bo = (uint32_t)((i & 1) * 8192);

        uint32_t sacc[8][2];
        #pragma unroll
        for (int nf = 0; nf < 8; ++nf) { sacc[nf][0] = 0u; sacc[nf][1] = 0u; }
        #pragma unroll
        for (int np = 0; np < 4; ++np) {
            uint32_t bA[8], bB[8];
            uint32_t base0 = sb + bo + (uint32_t)(2 * np * 1024);
            ldsm4(bA + 0, base0 + sOff0);
            ldsm4(bA + 4, base0 + sOff1);
            ldsm4(bB + 0, base0 + 1024 + sOff0);
            ldsm4(bB + 4, base0 + 1024 + sOff1);
            #pragma unroll
            for (int s = 0; s < 4; ++s) {
                mma16816h(sacc[2 * np],     qa[s], bA[2 * s], bA[2 * s + 1]);
                mma16816h(sacc[2 * np + 1], qa[s], bB[2 * s], bB[2 * s + 1]);
            }
        }

        #pragma unroll
        for (int u = 0; u < 4; ++u) {
            uint32_t pa[4];
            pa[0] = ex2h2(sacc[2 * u][0]);
            pa[1] = ex2h2(sacc[2 * u][1]);
            pa[2] = ex2h2(sacc[2 * u + 1][0]);
            pa[3] = ex2h2(sacc[2 * u + 1][1]);
            mma16816(lfrag, pa, ONES_H2, ONES_H2);
            #pragma unroll
            for (int dfp = 0; dfp < 4; ++dfp) {
                uint32_t voff = bo + vRow + (uint32_t)(u * 2048)
                              + (((uint32_t)(dfp * 32) + wD) ^ xr);
                uint32_t vh[4];
                ldsm4t(vh, sb + voff);
                mma16816(oacc[2 * dfp],     pa, vh[0], vh[1]);
                mma16816(oacc[2 * dfp + 1], pa, vh[2], vh[3]);
            }
        }

        if (i < 31) {
            store_half((i + 1) & 1);
            if (i < 30) load_half(i + 2);
            __syncthreads();
        }
    }

    float inv0 = 1.f / lfrag[0], inv1 = 1.f / lfrag[2];

    size_t r0 = ((size_t)b * LQ_ + (size_t)qb * 128 + wid * 16 + g) * DIM_ + h * DK_;
    size_t r1 = r0 + 8 * DIM_;
    #pragma unroll
    for (int df = 0; df < 8; ++df) {
        int c = df * 8 + 2 * t;
        *(uint32_t*)((char*)Xh + (r0 + c) * 2) =
            pack_h2(oacc[df][0] * inv0, oacc[df][1] * inv0);
        *(uint32_t*)((char*)Xh + (r1 + c) * 2) =
            pack_h2(oacc[df][2] * inv1, oacc[df][3] * inv1);
    }
}

// ---------------------------------------------------------------------------
extern "C" void kernel_launch(void* const* d_in, const int* in_sizes, int n_in,
                              void* d_out, int out_size) {
    const float* L  = (const float*)d_in[0];
    const float* G  = (const float*)d_in[1];
    const float* Wq = (const float*)d_in[2];
    const float* bq = (const float*)d_in[3];
    const float* Wo = (const float*)d_in[4];
    const float* bo = (const float*)d_in[5];
    float* out = (float*)d_out;

    __half *xh, *wqh, *woh, *wol;
    cudaGetSymbolAddress((void**)&xh,  g_xh);
    cudaGetSymbolAddress((void**)&wqh, g_wqh);
    cudaGetSymbolAddress((void**)&woh, g_woh);
    cudaGetSymbolAddress((void**)&wol, g_wol);

    cudaFuncSetAttribute(gemm2_kernel,
                         cudaFuncAttributeMaxDynamicSharedMemorySize, GEMM2_SMEM);

    dim3 gGemm(DIM_ / 64, M_ / 128);            // (8, 32) = 256 CTAs
    dim3 gAttn(LQ_ / 128, H_, B_);              // (2, 8, 16) = 256 CTAs
    int prepBlocks = (2 * NW16 + 255) / 256;    // 128 CTAs

    prep_kernel<<<prepBlocks, 256>>>(Wq, Wo);
    attn_fused_kernel<<<gAttn, 256>>>(L, G, wqh, bq, xh);
    gemm2_kernel<<<gGemm, 256, GEMM2_SMEM>>>(xh, woh, wol, bo, out);
}